// round 2
// baseline (speedup 1.0000x reference)
#include <cuda_runtime.h>
#include <math.h>

#define Nn   50000
#define Gg   100
#define NPGc 500
#define INf  128
#define Hh   256
#define Ee   800000
#define SPLIT 10
#define RPS   50

// ---------------- scratch (static __device__, no allocs) ----------------
__device__ float g_h   [Nn * Hh];
__device__ float g_xn  [Nn * Hh];
__device__ float g_m   [Nn * Hh];
__device__ float g_c   [Nn * Hh];
__device__ float g_f   [Nn * Hh];
__device__ float g_g   [Nn * Hh];
__device__ float g_sim [(size_t)Gg * NPGc * NPGc];
__device__ int   g_knn [Nn * 3];
__device__ float g_deg [Nn];
__device__ float g_dinv[Nn];
__device__ float g_s1  [Gg * Hh];
__device__ float g_s2  [Gg * Hh];
__device__ float g_alpha[Gg * Hh];
__device__ float g_beta [Gg * Hh];

// ---------------- small utility kernels ----------------
__global__ void zerof_k(float* p, int n) {
    int i = blockIdx.x * blockDim.x + threadIdx.x;
    if (i < n) p[i] = 0.0f;
}

__global__ void zstats_k() {
    int i = blockIdx.x * blockDim.x + threadIdx.x;
    if (i < Gg * Hh) { g_s1[i] = 0.0f; g_s2[i] = 0.0f; }
}

__global__ void deg_init_k() {
    int i = blockIdx.x * blockDim.x + threadIdx.x;
    if (i < Nn) g_deg[i] = 1.0f;   // self loop
}

__global__ void deg_count_k(const int* __restrict__ dst) {
    int e = blockIdx.x * blockDim.x + threadIdx.x;
    if (e < Ee) atomicAdd(&g_deg[dst[e]], 1.0f);
}

__global__ void dinv_k() {
    int i = blockIdx.x * blockDim.x + threadIdx.x;
    if (i < Nn) g_dinv[i] = rsqrtf(g_deg[i]);
}

// ---------------- SGEMM: C[M,256] = A[M,Kd] @ B[Kd,256] (+epilogue) ----------------
// EPI 0: C = acc
// EPI 1: C = acc + bias[col]
// EPI 2: g = sigmoid(acc + gacc); hout = g*hc + (1-g)*fb + hprev   (C unused)
template <int EPI>
__global__ __launch_bounds__(256) void sgemm_k(
    const float* __restrict__ A, const float* __restrict__ B, float* __restrict__ C,
    int M, int Kd, const float* __restrict__ bias,
    const float* __restrict__ gacc, const float* __restrict__ hc,
    const float* __restrict__ fb, const float* __restrict__ hprev,
    float* __restrict__ hout)
{
    __shared__ float As[8][128];
    __shared__ float Bs[8][128];

    int tid = threadIdx.x;
    int m0 = blockIdx.y * 128, n0 = blockIdx.x * 128;
    int aRow = tid >> 1, aK = (tid & 1) * 4;
    int bRow = tid >> 5, bCol = (tid & 31) * 4;
    int tr = tid >> 4, tc = tid & 15;

    float acc[8][8];
#pragma unroll
    for (int i = 0; i < 8; i++)
#pragma unroll
        for (int j = 0; j < 8; j++) acc[i][j] = 0.0f;

    bool aval = (m0 + aRow) < M;
    const float* Abase = A + (size_t)(m0 + aRow) * Kd + aK;

    for (int k0 = 0; k0 < Kd; k0 += 8) {
        float4 av = aval ? *(const float4*)(Abase + k0) : make_float4(0.f, 0.f, 0.f, 0.f);
        As[aK + 0][aRow] = av.x; As[aK + 1][aRow] = av.y;
        As[aK + 2][aRow] = av.z; As[aK + 3][aRow] = av.w;
        float4 bv = *(const float4*)(B + (size_t)(k0 + bRow) * 256 + n0 + bCol);
        *(float4*)&Bs[bRow][bCol] = bv;
        __syncthreads();
#pragma unroll
        for (int kk = 0; kk < 8; kk++) {
            float a[8], b[8];
#pragma unroll
            for (int i = 0; i < 8; i++) a[i] = As[kk][tr * 8 + i];
#pragma unroll
            for (int j = 0; j < 8; j++) b[j] = Bs[kk][tc * 8 + j];
#pragma unroll
            for (int i = 0; i < 8; i++)
#pragma unroll
                for (int j = 0; j < 8; j++) acc[i][j] += a[i] * b[j];
        }
        __syncthreads();
    }

#pragma unroll
    for (int i = 0; i < 8; i++) {
        int row = m0 + tr * 8 + i;
        if (row >= M) break;
        size_t base = (size_t)row * 256 + n0 + tc * 8;
#pragma unroll
        for (int j = 0; j < 8; j++) {
            float v = acc[i][j];
            if (EPI == 0) {
                C[base + j] = v;
            } else if (EPI == 1) {
                C[base + j] = v + bias[n0 + tc * 8 + j];
            } else {
                float s = v + gacc[base + j];
                float gg = 1.0f / (1.0f + expf(-s));
                hout[base + j] = gg * hc[base + j] + (1.0f - gg) * fb[base + j] + hprev[base + j];
            }
        }
    }
}

// ---------------- row normalize (for cosine knn) ----------------
__global__ void rownorm_k() {
    int row = blockIdx.x;
    int t = threadIdx.x;                // 64 threads, 4 floats each
    float4 v = *(const float4*)(g_h + (size_t)row * Hh + t * 4);
    float s = v.x * v.x + v.y * v.y + v.z * v.z + v.w * v.w;
    __shared__ float sh[64];
    sh[t] = s;
    __syncthreads();
    for (int off = 32; off > 0; off >>= 1) {
        if (t < off) sh[t] += sh[t + off];
        __syncthreads();
    }
    float inv = 1.0f / (sqrtf(sh[0]) + 1e-12f);
    float4 o = make_float4(v.x * inv, v.y * inv, v.z * inv, v.w * inv);
    *(float4*)(g_xn + (size_t)row * Hh + t * 4) = o;
}

// ---------------- batched sim = Xn @ Xn^T per graph ----------------
__global__ __launch_bounds__(256) void simgemm_k() {
    int g = blockIdx.z;
    const float* A = g_xn + (size_t)g * NPGc * Hh;
    int i0 = blockIdx.y * 64, j0 = blockIdx.x * 64;
    __shared__ float As[16][68];
    __shared__ float Bs[16][68];
    int tid = threadIdx.x;
    int lRow = tid >> 2, lK = (tid & 3) * 4;
    int tr = tid >> 4, tc = tid & 15;
    float acc[4][4];
#pragma unroll
    for (int i = 0; i < 4; i++)
#pragma unroll
        for (int j = 0; j < 4; j++) acc[i][j] = 0.0f;

    for (int k0 = 0; k0 < Hh; k0 += 16) {
        int ra = i0 + lRow;
        float4 av = (ra < NPGc) ? *(const float4*)(A + (size_t)ra * Hh + k0 + lK)
                                : make_float4(0.f, 0.f, 0.f, 0.f);
        As[lK + 0][lRow] = av.x; As[lK + 1][lRow] = av.y;
        As[lK + 2][lRow] = av.z; As[lK + 3][lRow] = av.w;
        int rb = j0 + lRow;
        float4 bv = (rb < NPGc) ? *(const float4*)(A + (size_t)rb * Hh + k0 + lK)
                                : make_float4(0.f, 0.f, 0.f, 0.f);
        Bs[lK + 0][lRow] = bv.x; Bs[lK + 1][lRow] = bv.y;
        Bs[lK + 2][lRow] = bv.z; Bs[lK + 3][lRow] = bv.w;
        __syncthreads();
#pragma unroll
        for (int kk = 0; kk < 16; kk++) {
            float a[4], b[4];
#pragma unroll
            for (int i = 0; i < 4; i++) a[i] = As[kk][tr * 4 + i];
#pragma unroll
            for (int j = 0; j < 4; j++) b[j] = Bs[kk][tc * 4 + j];
#pragma unroll
            for (int i = 0; i < 4; i++)
#pragma unroll
                for (int j = 0; j < 4; j++) acc[i][j] += a[i] * b[j];
        }
        __syncthreads();
    }
    float* S = g_sim + (size_t)g * NPGc * NPGc;
#pragma unroll
    for (int i = 0; i < 4; i++) {
        int ii = i0 + tr * 4 + i;
        if (ii >= NPGc) continue;
#pragma unroll
        for (int j = 0; j < 4; j++) {
            int jj = j0 + tc * 4 + j;
            if (jj < NPGc) S[(size_t)ii * NPGc + jj] = acc[i][j];
        }
    }
}

// ---------------- top-3 per row (jax top_k tie semantics) ----------------
#define TK_INS(v, id)                                                      \
    do {                                                                    \
        float _v = (v); int _i = (id);                                      \
        if (_v > bv0 || (_v == bv0 && _i < bi0)) {                          \
            bv2 = bv1; bi2 = bi1; bv1 = bv0; bi1 = bi0; bv0 = _v; bi0 = _i; \
        } else if (_v > bv1 || (_v == bv1 && _i < bi1)) {                   \
            bv2 = bv1; bi2 = bi1; bv1 = _v; bi1 = _i;                       \
        } else if (_v > bv2 || (_v == bv2 && _i < bi2)) {                   \
            bv2 = _v; bi2 = _i;                                             \
        }                                                                   \
    } while (0)

__global__ void topk_k() {
    int r = blockIdx.x * 8 + (threadIdx.x >> 5);
    int lane = threadIdx.x & 31;
    if (r >= Nn) return;
    int g = r / NPGc;
    const float* row = g_sim + (size_t)g * NPGc * NPGc + (size_t)(r % NPGc) * NPGc;
    int goff = g * NPGc;
    float bv0 = -1e30f, bv1 = -1e30f, bv2 = -1e30f;
    int bi0 = 0x7fffffff, bi1 = 0x7fffffff, bi2 = 0x7fffffff;
    for (int j = lane; j < NPGc; j += 32) {
        TK_INS(row[j], goff + j);
    }
    for (int off = 16; off > 0; off >>= 1) {
        float ov0 = __shfl_down_sync(0xffffffff, bv0, off);
        float ov1 = __shfl_down_sync(0xffffffff, bv1, off);
        float ov2 = __shfl_down_sync(0xffffffff, bv2, off);
        int oi0 = __shfl_down_sync(0xffffffff, bi0, off);
        int oi1 = __shfl_down_sync(0xffffffff, bi1, off);
        int oi2 = __shfl_down_sync(0xffffffff, bi2, off);
        TK_INS(ov0, oi0); TK_INS(ov1, oi1); TK_INS(ov2, oi2);
    }
    if (lane == 0) {
        g_knn[r * 3 + 0] = bi0;
        g_knn[r * 3 + 1] = bi1;
        g_knn[r * 3 + 2] = bi2;
    }
}

// ---------------- GCN aggregation ----------------
// self-loop init: c = m * dinv^2 + bias
__global__ void conv_self_k(const float* __restrict__ bias) {
    int t = blockIdx.x * blockDim.x + threadIdx.x;
    if (t >= Nn * 64) return;
    int n = t >> 6, q = t & 63;
    float d = g_dinv[n];
    float co = d * d;
    float4 mv = ((const float4*)g_m)[(size_t)n * 64 + q];
    float4 bv = ((const float4*)bias)[q];
    float4 o = make_float4(mv.x * co + bv.x, mv.y * co + bv.y,
                           mv.z * co + bv.z, mv.w * co + bv.w);
    ((float4*)g_c)[(size_t)n * 64 + q] = o;
}

__global__ void edge_scatter_k(const int* __restrict__ src, const int* __restrict__ dst) {
    long long t = (long long)blockIdx.x * blockDim.x + threadIdx.x;
    if (t >= (long long)Ee * 64) return;
    int e = (int)(t >> 6), q = (int)(t & 63);
    int s = src[e], d = dst[e];
    float co = g_dinv[s] * g_dinv[d];
    float4 mv = ((const float4*)g_m)[(size_t)s * 64 + q];
    float* o = g_c + (size_t)d * 256 + q * 4;
    atomicAdd(o + 0, mv.x * co);
    atomicAdd(o + 1, mv.y * co);
    atomicAdd(o + 2, mv.z * co);
    atomicAdd(o + 3, mv.w * co);
}

// knn branch: deg = K+1 = 4 uniformly -> coef = 0.25, gather (atomic-free)
__global__ void knn_agg_k(const float* __restrict__ bias) {
    int t = blockIdx.x * blockDim.x + threadIdx.x;
    if (t >= Nn * 64) return;
    int n = t >> 6, q = t & 63;
    int i0 = g_knn[n * 3 + 0], i1 = g_knn[n * 3 + 1], i2 = g_knn[n * 3 + 2];
    float4 a = ((const float4*)g_m)[(size_t)n * 64 + q];
    float4 b = ((const float4*)g_m)[(size_t)i0 * 64 + q];
    float4 c = ((const float4*)g_m)[(size_t)i1 * 64 + q];
    float4 d = ((const float4*)g_m)[(size_t)i2 * 64 + q];
    float4 bv = ((const float4*)bias)[q];
    float4 o = make_float4(0.25f * (a.x + b.x + c.x + d.x) + bv.x,
                           0.25f * (a.y + b.y + c.y + d.y) + bv.y,
                           0.25f * (a.z + b.z + c.z + d.z) + bv.z,
                           0.25f * (a.w + b.w + c.w + d.w) + bv.w);
    ((float4*)g_f)[(size_t)n * 64 + q] = o;
}

// ---------------- GraphNorm ----------------
__global__ void stats_k(const float* __restrict__ buf) {
    int b = blockIdx.x;
    int g = b / SPLIT, sp = b % SPLIT;
    int cc = threadIdx.x;
    int r0 = g * NPGc + sp * RPS;
    float s1 = 0.0f, s2 = 0.0f;
    for (int r = 0; r < RPS; r++) {
        float v = buf[(size_t)(r0 + r) * Hh + cc];
        s1 += v; s2 += v * v;
    }
    atomicAdd(&g_s1[g * Hh + cc], s1);
    atomicAdd(&g_s2[g * Hh + cc], s2);
}

__global__ void finalize_k(const float* __restrict__ w, const float* __restrict__ b,
                           const float* __restrict__ ms) {
    int i = blockIdx.x * blockDim.x + threadIdx.x;
    if (i >= Gg * Hh) return;
    int cc = i & 255;
    float mean = g_s1[i] * (1.0f / NPGc);
    float ex2 = g_s2[i] * (1.0f / NPGc);
    float m = ms[cc];
    float var = ex2 - mean * mean * m * (2.0f - m);
    float a = w[cc] * rsqrtf(var + 1e-5f);
    g_alpha[i] = a;
    g_beta[i] = b[cc] - a * m * mean;
}

__global__ void apply_leaky_k(float* __restrict__ buf) {
    int t = blockIdx.x * blockDim.x + threadIdx.x;
    if (t >= Nn * 64) return;
    int n = t >> 6, q = t & 63;
    int g = n / NPGc;
    float4 v = ((const float4*)buf)[(size_t)n * 64 + q];
    float4 a = ((const float4*)g_alpha)[(size_t)g * 64 + q];
    float4 b = ((const float4*)g_beta)[(size_t)g * 64 + q];
    float y0 = a.x * v.x + b.x, y1 = a.y * v.y + b.y;
    float y2 = a.z * v.z + b.z, y3 = a.w * v.w + b.w;
    y0 = y0 > 0.f ? y0 : 0.01f * y0;
    y1 = y1 > 0.f ? y1 : 0.01f * y1;
    y2 = y2 > 0.f ? y2 : 0.01f * y2;
    y3 = y3 > 0.f ? y3 : 0.01f * y3;
    ((float4*)buf)[(size_t)n * 64 + q] = make_float4(y0, y1, y2, y3);
}

// ---------------- pooling ----------------
__global__ void pool_k(const float* __restrict__ buf, float* __restrict__ out, float wgt) {
    int b = blockIdx.x;
    int g = b / SPLIT, sp = b % SPLIT;
    int cc = threadIdx.x;
    int r0 = g * NPGc + sp * RPS;
    float s = 0.0f;
    for (int r = 0; r < RPS; r++) s += buf[(size_t)(r0 + r) * Hh + cc];
    atomicAdd(&out[g * Hh + cc], s * wgt * (1.0f / NPGc));
}

// ---------------- launch ----------------
extern "C" void kernel_launch(void* const* d_in, const int* in_sizes, int n_in,
                              void* d_out, int out_size) {
    const float* x       = (const float*)d_in[0];
    const int*   ei      = (const int*)d_in[1];
    const float* emb_W   = (const float*)d_in[3];
    const float* emb_b   = (const float*)d_in[4];
    const float* conv_W  = (const float*)d_in[5];
    const float* conv_b  = (const float*)d_in[6];
    const float* fconv_W = (const float*)d_in[7];
    const float* fconv_b = (const float*)d_in[8];
    const float* norm_w  = (const float*)d_in[9];
    const float* norm_b  = (const float*)d_in[10];
    const float* norm_ms = (const float*)d_in[11];
    const float* fnorm_w = (const float*)d_in[12];
    const float* fnorm_b = (const float*)d_in[13];
    const float* fnorm_ms= (const float*)d_in[14];
    const float* gate_W  = (const float*)d_in[15];
    const float* gate_b  = (const float*)d_in[16];
    float* out = (float*)d_out;

    const int* src = ei;
    const int* dst = ei + Ee;

    float *h, *cbuf, *fbuf, *gbuf, *m;
    cudaGetSymbolAddress((void**)&h, g_h);
    cudaGetSymbolAddress((void**)&cbuf, g_c);
    cudaGetSymbolAddress((void**)&fbuf, g_f);
    cudaGetSymbolAddress((void**)&gbuf, g_g);
    cudaGetSymbolAddress((void**)&m, g_m);

    const int TPB = 256;
    const int MB = (Nn + 127) / 128;     // 391 M-tiles
    dim3 gemm_grid(2, MB);

    // zero output (poisoned by harness)
    zerof_k<<<(Gg * Hh + TPB - 1) / TPB, TPB>>>(out, Gg * Hh);

    // degrees (self loop included via init=1)
    deg_init_k<<<(Nn + TPB - 1) / TPB, TPB>>>();
    deg_count_k<<<(Ee + TPB - 1) / TPB, TPB>>>(dst);
    dinv_k<<<(Nn + TPB - 1) / TPB, TPB>>>();

    // h = x @ emb_W + emb_b
    sgemm_k<1><<<gemm_grid, TPB>>>(x, emb_W, h, Nn, INf, emb_b,
                                   nullptr, nullptr, nullptr, nullptr, nullptr);

    // cosine knn on h
    rownorm_k<<<Nn, 64>>>();
    simgemm_k<<<dim3(8, 8, Gg), TPB>>>();
    topk_k<<<(Nn + 7) / 8, TPB>>>();

    float pool_w[2] = {1.0f, 2.0f};   // gf = pool(x0) + 2*pool(x1)  (all_x[i-1] quirk)

    for (int li = 0; li < 2; li++) {
        // ---- conv branch: m = h @ W; c = GCN-agg(m) + b ----
        sgemm_k<0><<<gemm_grid, TPB>>>(h, conv_W + li * Hh * Hh, m, Nn, Hh, nullptr,
                                       nullptr, nullptr, nullptr, nullptr, nullptr);
        conv_self_k<<<(Nn * 64 + TPB - 1) / TPB, TPB>>>(conv_b + li * Hh);
        edge_scatter_k<<<(int)(((long long)Ee * 64 + TPB - 1) / TPB), TPB>>>(src, dst);
        zstats_k<<<(Gg * Hh + TPB - 1) / TPB, TPB>>>();
        stats_k<<<Gg * SPLIT, TPB>>>(cbuf);
        finalize_k<<<(Gg * Hh + TPB - 1) / TPB, TPB>>>(norm_w + li * Hh, norm_b + li * Hh,
                                                       norm_ms + li * Hh);
        apply_leaky_k<<<(Nn * 64 + TPB - 1) / TPB, TPB>>>(cbuf);

        // ---- feature branch: fm = c @ fW; f = knn-agg(fm) + fb ----
        sgemm_k<0><<<gemm_grid, TPB>>>(cbuf, fconv_W + li * Hh * Hh, m, Nn, Hh, nullptr,
                                       nullptr, nullptr, nullptr, nullptr, nullptr);
        knn_agg_k<<<(Nn * 64 + TPB - 1) / TPB, TPB>>>(fconv_b + li * Hh);
        zstats_k<<<(Gg * Hh + TPB - 1) / TPB, TPB>>>();
        stats_k<<<Gg * SPLIT, TPB>>>(fbuf);
        finalize_k<<<(Gg * Hh + TPB - 1) / TPB, TPB>>>(fnorm_w + li * Hh, fnorm_b + li * Hh,
                                                       fnorm_ms + li * Hh);
        apply_leaky_k<<<(Nn * 64 + TPB - 1) / TPB, TPB>>>(fbuf);

        // ---- gate: g = sigmoid(c@W1 + f@W2 + b); h = g*c + (1-g)*f + h ----
        sgemm_k<1><<<gemm_grid, TPB>>>(cbuf, gate_W, gbuf, Nn, Hh, gate_b,
                                       nullptr, nullptr, nullptr, nullptr, nullptr);
        sgemm_k<2><<<gemm_grid, TPB>>>(fbuf, gate_W + Hh * Hh, gbuf, Nn, Hh, nullptr,
                                       gbuf, cbuf, fbuf, h, h);

        // ---- weighted pooled accumulate ----
        pool_k<<<Gg * SPLIT, TPB>>>(h, out, pool_w[li]);
    }
    (void)in_sizes; (void)n_in; (void)out_size;
}

// round 3
// speedup vs baseline: 1.9425x; 1.9425x over previous
#include <cuda_runtime.h>
#include <math.h>
#include <stdint.h>

#define Nn   50000
#define Gg   100
#define NPGc 500
#define INf  128
#define Hh   256
#define Ee   800000
#define SPLIT 10
#define RPS   50

// ---------------- scratch (static __device__, no allocs) ----------------
__device__ float g_h   [Nn * Hh];
__device__ float g_xn  [Nn * Hh];
__device__ float g_m   [Nn * Hh];
__device__ float g_c   [Nn * Hh];
__device__ float g_f   [Nn * Hh];
__device__ float g_g   [Nn * Hh];
__device__ float g_sim [(size_t)Gg * NPGc * NPGc];
__device__ int   g_knn [Nn * 3];
__device__ int   g_cnt [Nn];
__device__ float g_dinv[Nn];
__device__ int   g_scan[Nn];
__device__ int   g_off [Nn];
__device__ int   g_fill[Nn];
__device__ int   g_bsum[256];
__device__ int   g_bbase[256];
__device__ int   g_esrc[Ee];
__device__ float g_ecoef[Ee];
__device__ float g_s1  [Gg * Hh];
__device__ float g_s2  [Gg * Hh];
__device__ float g_alpha[Gg * Hh];
__device__ float g_beta [Gg * Hh];

// ---------------- small utility kernels ----------------
__global__ void zerof_k(float* p, int n) {
    int i = blockIdx.x * blockDim.x + threadIdx.x;
    if (i < n) p[i] = 0.0f;
}
__global__ void zstats_k() {
    int i = blockIdx.x * blockDim.x + threadIdx.x;
    if (i < Gg * Hh) { g_s1[i] = 0.0f; g_s2[i] = 0.0f; }
}
__global__ void cnt_zero_k() {
    int i = blockIdx.x * blockDim.x + threadIdx.x;
    if (i < Nn) g_cnt[i] = 0;
}
__global__ void cnt_count_k(const int* __restrict__ dst) {
    int e = blockIdx.x * blockDim.x + threadIdx.x;
    if (e < Ee) atomicAdd(&g_cnt[dst[e]], 1);
}
__global__ void dinv_k() {
    int i = blockIdx.x * blockDim.x + threadIdx.x;
    if (i < Nn) g_dinv[i] = rsqrtf((float)g_cnt[i] + 1.0f);
}

// ---------------- CSR build (scan + fill) ----------------
__global__ void scan1_k() {
    __shared__ int sh[256];
    int i = blockIdx.x * 256 + threadIdx.x;
    int v = (i < Nn) ? g_cnt[i] : 0;
    sh[threadIdx.x] = v;
    __syncthreads();
    for (int off = 1; off < 256; off <<= 1) {
        int t = (threadIdx.x >= off) ? sh[threadIdx.x - off] : 0;
        __syncthreads();
        sh[threadIdx.x] += t;
        __syncthreads();
    }
    if (i < Nn) g_scan[i] = sh[threadIdx.x];
    if (threadIdx.x == 255) g_bsum[blockIdx.x] = sh[255];
}
__global__ void scan2_k(int nblk) {
    __shared__ int sh[256];
    int b = threadIdx.x;
    int v = (b < nblk) ? g_bsum[b] : 0;
    sh[b] = v;
    __syncthreads();
    for (int off = 1; off < 256; off <<= 1) {
        int t = (b >= off) ? sh[b - off] : 0;
        __syncthreads();
        sh[b] += t;
        __syncthreads();
    }
    if (b < nblk) g_bbase[b] = sh[b] - v;   // exclusive
}
__global__ void scan3_k() {
    int i = blockIdx.x * blockDim.x + threadIdx.x;
    if (i < Nn) {
        int off = g_scan[i] - g_cnt[i] + g_bbase[i >> 8];
        g_off[i] = off;
        g_fill[i] = off;
    }
}
__global__ void fill_k(const int* __restrict__ src, const int* __restrict__ dst) {
    int e = blockIdx.x * blockDim.x + threadIdx.x;
    if (e >= Ee) return;
    int s = src[e], d = dst[e];
    int p = atomicAdd(&g_fill[d], 1);
    g_esrc[p] = s;
    g_ecoef[p] = g_dinv[s] * g_dinv[d];
}

// ---------------- fp32 SGEMM for emb: C[M,256] = A[M,128] @ B[128,256] + bias ----------------
__global__ __launch_bounds__(256) void sgemm_emb_k(
    const float* __restrict__ A, const float* __restrict__ B, float* __restrict__ C,
    int M, int Kd, const float* __restrict__ bias)
{
    __shared__ float As[8][128];
    __shared__ float Bs[8][128];
    int tid = threadIdx.x;
    int m0 = blockIdx.y * 128, n0 = blockIdx.x * 128;
    int aRow = tid >> 1, aK = (tid & 1) * 4;
    int bRow = tid >> 5, bCol = (tid & 31) * 4;
    int tr = tid >> 4, tc = tid & 15;
    float acc[8][8];
#pragma unroll
    for (int i = 0; i < 8; i++)
#pragma unroll
        for (int j = 0; j < 8; j++) acc[i][j] = 0.0f;
    bool aval = (m0 + aRow) < M;
    const float* Abase = A + (size_t)(m0 + aRow) * Kd + aK;
    for (int k0 = 0; k0 < Kd; k0 += 8) {
        float4 av = aval ? *(const float4*)(Abase + k0) : make_float4(0.f, 0.f, 0.f, 0.f);
        As[aK + 0][aRow] = av.x; As[aK + 1][aRow] = av.y;
        As[aK + 2][aRow] = av.z; As[aK + 3][aRow] = av.w;
        float4 bv = *(const float4*)(B + (size_t)(k0 + bRow) * 256 + n0 + bCol);
        *(float4*)&Bs[bRow][bCol] = bv;
        __syncthreads();
#pragma unroll
        for (int kk = 0; kk < 8; kk++) {
            float a[8], b[8];
#pragma unroll
            for (int i = 0; i < 8; i++) a[i] = As[kk][tr * 8 + i];
#pragma unroll
            for (int j = 0; j < 8; j++) b[j] = Bs[kk][tc * 8 + j];
#pragma unroll
            for (int i = 0; i < 8; i++)
#pragma unroll
                for (int j = 0; j < 8; j++) acc[i][j] += a[i] * b[j];
        }
        __syncthreads();
    }
#pragma unroll
    for (int i = 0; i < 8; i++) {
        int row = m0 + tr * 8 + i;
        if (row >= M) break;
        size_t base = (size_t)row * 256 + n0 + tc * 8;
#pragma unroll
        for (int j = 0; j < 8; j++) C[base + j] = acc[i][j] + bias[n0 + tc * 8 + j];
    }
}

// ---------------- TF32 mma GEMM: C[M,256] = A[M,256] @ B[256,256] (+epilogue) ----------------
// EPI 0: C = acc
// EPI 1: C = acc + bias[col]
// EPI 2: g = sigmoid(acc + gacc); hout = g*hc + (1-g)*fb + hprev
__device__ __forceinline__ uint32_t f2tf(float f) {
    uint32_t u;
    asm("cvt.rna.tf32.f32 %0, %1;" : "=r"(u) : "f"(f));
    return u;
}
__device__ __forceinline__ void mma8(float* c, const uint32_t* a, const uint32_t* b) {
    asm volatile(
        "mma.sync.aligned.m16n8k8.row.col.f32.tf32.tf32.f32 "
        "{%0,%1,%2,%3}, {%4,%5,%6,%7}, {%8,%9}, {%0,%1,%2,%3};"
        : "+f"(c[0]), "+f"(c[1]), "+f"(c[2]), "+f"(c[3])
        : "r"(a[0]), "r"(a[1]), "r"(a[2]), "r"(a[3]), "r"(b[0]), "r"(b[1]));
}

template <int EPI>
__global__ __launch_bounds__(256) void mmagemm_k(
    const float* __restrict__ A, const float* __restrict__ B, float* __restrict__ C,
    int M, const float* __restrict__ bias,
    const float* __restrict__ gacc, const float* __restrict__ hc,
    const float* __restrict__ fb, const float* __restrict__ hprev,
    float* __restrict__ hout)
{
    __shared__ uint32_t As[128][40];   // [m][k], pad 40 -> frag loads conflict-free
    __shared__ uint32_t Bs[32][136];   // [k][n], pad 136 -> frag loads conflict-free

    int tid = threadIdx.x;
    int wid = tid >> 5, lane = tid & 31;
    int m0 = blockIdx.y * 128, n0 = blockIdx.x * 128;
    int wm = (wid & 3) * 32, wn = (wid >> 2) * 64;
    int group = lane >> 2, tig = lane & 3;

    float acc[2][8][4];
#pragma unroll
    for (int mt = 0; mt < 2; mt++)
#pragma unroll
        for (int nt = 0; nt < 8; nt++)
#pragma unroll
            for (int q = 0; q < 4; q++) acc[mt][nt][q] = 0.0f;

    int arow = tid >> 3, acol = (tid & 7) * 4;       // A: 32 rows/iter x 4 iters, float4 on K
    int brow = tid >> 5, bcol = (tid & 31) * 4;      // B: 8 k-rows/iter x 4 iters, float4 on N

    float4 pa[4], pb[4];
#pragma unroll
    for (int i = 0; i < 4; i++) {
        int r = m0 + arow + 32 * i;
        pa[i] = (r < M) ? *(const float4*)(A + (size_t)r * 256 + acol)
                        : make_float4(0.f, 0.f, 0.f, 0.f);
        pb[i] = *(const float4*)(B + (size_t)(brow + 8 * i) * 256 + n0 + bcol);
    }

    for (int kt = 0; kt < 8; kt++) {
#pragma unroll
        for (int i = 0; i < 4; i++) {
            uint4 ua = make_uint4(f2tf(pa[i].x), f2tf(pa[i].y), f2tf(pa[i].z), f2tf(pa[i].w));
            *(uint4*)&As[arow + 32 * i][acol] = ua;
            uint4 ub = make_uint4(f2tf(pb[i].x), f2tf(pb[i].y), f2tf(pb[i].z), f2tf(pb[i].w));
            *(uint4*)&Bs[brow + 8 * i][bcol] = ub;
        }
        __syncthreads();

        if (kt < 7) {
            int k0 = (kt + 1) * 32;
#pragma unroll
            for (int i = 0; i < 4; i++) {
                int r = m0 + arow + 32 * i;
                pa[i] = (r < M) ? *(const float4*)(A + (size_t)r * 256 + k0 + acol)
                                : make_float4(0.f, 0.f, 0.f, 0.f);
                pb[i] = *(const float4*)(B + (size_t)(k0 + brow + 8 * i) * 256 + n0 + bcol);
            }
        }

#pragma unroll
        for (int ks = 0; ks < 4; ks++) {
            int kb = ks * 8;
            uint32_t afr[2][4];
#pragma unroll
            for (int mt = 0; mt < 2; mt++) {
                int r = wm + mt * 16 + group;
                afr[mt][0] = As[r][kb + tig];
                afr[mt][1] = As[r + 8][kb + tig];
                afr[mt][2] = As[r][kb + tig + 4];
                afr[mt][3] = As[r + 8][kb + tig + 4];
            }
            uint32_t bfr[8][2];
#pragma unroll
            for (int nt = 0; nt < 8; nt++) {
                int cc = wn + nt * 8 + group;
                bfr[nt][0] = Bs[kb + tig][cc];
                bfr[nt][1] = Bs[kb + tig + 4][cc];
            }
#pragma unroll
            for (int mt = 0; mt < 2; mt++)
#pragma unroll
                for (int nt = 0; nt < 8; nt++) mma8(acc[mt][nt], afr[mt], bfr[nt]);
        }
        __syncthreads();
    }

    // epilogue
#pragma unroll
    for (int mt = 0; mt < 2; mt++) {
        int rowA = m0 + wm + mt * 16 + group;
        int rowB = rowA + 8;
#pragma unroll
        for (int nt = 0; nt < 8; nt++) {
            int col = n0 + wn + nt * 8 + 2 * tig;
#pragma unroll
            for (int half = 0; half < 2; half++) {
                int row = half ? rowB : rowA;
                if (row >= M) continue;
                float v0 = acc[mt][nt][half * 2 + 0];
                float v1 = acc[mt][nt][half * 2 + 1];
                size_t base = (size_t)row * 256 + col;
                if (EPI == 0) {
                    C[base] = v0; C[base + 1] = v1;
                } else if (EPI == 1) {
                    C[base] = v0 + bias[col];
                    C[base + 1] = v1 + bias[col + 1];
                } else {
                    float s0 = v0 + gacc[base], s1 = v1 + gacc[base + 1];
                    float g0 = 1.0f / (1.0f + expf(-s0));
                    float g1 = 1.0f / (1.0f + expf(-s1));
                    hout[base]     = g0 * hc[base]     + (1.0f - g0) * fb[base]     + hprev[base];
                    hout[base + 1] = g1 * hc[base + 1] + (1.0f - g1) * fb[base + 1] + hprev[base + 1];
                }
            }
        }
    }
}

// ---------------- row normalize (for cosine knn) ----------------
__global__ void rownorm_k() {
    int row = blockIdx.x;
    int t = threadIdx.x;
    float4 v = *(const float4*)(g_h + (size_t)row * Hh + t * 4);
    float s = v.x * v.x + v.y * v.y + v.z * v.z + v.w * v.w;
    __shared__ float sh[64];
    sh[t] = s;
    __syncthreads();
    for (int off = 32; off > 0; off >>= 1) {
        if (t < off) sh[t] += sh[t + off];
        __syncthreads();
    }
    float inv = 1.0f / (sqrtf(sh[0]) + 1e-12f);
    *(float4*)(g_xn + (size_t)row * Hh + t * 4) =
        make_float4(v.x * inv, v.y * inv, v.z * inv, v.w * inv);
}

// ---------------- sim = Xn @ Xn^T per graph, 128x128 tiles, fp32 ----------------
__global__ __launch_bounds__(256) void simbig_k() {
    int g = blockIdx.z;
    const float* X = g_xn + (size_t)g * NPGc * Hh;
    int i0 = blockIdx.y * 128, j0 = blockIdx.x * 128;
    __shared__ float As[8][128];
    __shared__ float Bs[8][128];
    int tid = threadIdx.x;
    int lRow = tid >> 1, lK = (tid & 1) * 4;
    int tr = tid >> 4, tc = tid & 15;
    float acc[8][8];
#pragma unroll
    for (int i = 0; i < 8; i++)
#pragma unroll
        for (int j = 0; j < 8; j++) acc[i][j] = 0.0f;

    bool avalid = (i0 + lRow) < NPGc;
    bool bvalid = (j0 + lRow) < NPGc;
    const float* Arow = X + (size_t)(i0 + lRow) * Hh + lK;
    const float* Brow = X + (size_t)(j0 + lRow) * Hh + lK;

    for (int k0 = 0; k0 < Hh; k0 += 8) {
        float4 av = avalid ? *(const float4*)(Arow + k0) : make_float4(0.f, 0.f, 0.f, 0.f);
        As[lK + 0][lRow] = av.x; As[lK + 1][lRow] = av.y;
        As[lK + 2][lRow] = av.z; As[lK + 3][lRow] = av.w;
        float4 bv = bvalid ? *(const float4*)(Brow + k0) : make_float4(0.f, 0.f, 0.f, 0.f);
        Bs[lK + 0][lRow] = bv.x; Bs[lK + 1][lRow] = bv.y;
        Bs[lK + 2][lRow] = bv.z; Bs[lK + 3][lRow] = bv.w;
        __syncthreads();
#pragma unroll
        for (int kk = 0; kk < 8; kk++) {
            float a[8], b[8];
#pragma unroll
            for (int i = 0; i < 8; i++) a[i] = As[kk][tr * 8 + i];
#pragma unroll
            for (int j = 0; j < 8; j++) b[j] = Bs[kk][tc * 8 + j];
#pragma unroll
            for (int i = 0; i < 8; i++)
#pragma unroll
                for (int j = 0; j < 8; j++) acc[i][j] += a[i] * b[j];
        }
        __syncthreads();
    }
    float* S = g_sim + (size_t)g * NPGc * NPGc;
#pragma unroll
    for (int i = 0; i < 8; i++) {
        int ii = i0 + tr * 8 + i;
        if (ii >= NPGc) continue;
#pragma unroll
        for (int j = 0; j < 8; j++) {
            int jj = j0 + tc * 8 + j;
            if (jj < NPGc) S[(size_t)ii * NPGc + jj] = acc[i][j];
        }
    }
}

// ---------------- top-3 per row (jax top_k tie semantics) ----------------
#define TK_INS(v, id)                                                      \
    do {                                                                    \
        float _v = (v); int _i = (id);                                      \
        if (_v > bv0 || (_v == bv0 && _i < bi0)) {                          \
            bv2 = bv1; bi2 = bi1; bv1 = bv0; bi1 = bi0; bv0 = _v; bi0 = _i; \
        } else if (_v > bv1 || (_v == bv1 && _i < bi1)) {                   \
            bv2 = bv1; bi2 = bi1; bv1 = _v; bi1 = _i;                       \
        } else if (_v > bv2 || (_v == bv2 && _i < bi2)) {                   \
            bv2 = _v; bi2 = _i;                                             \
        }                                                                   \
    } while (0)

__global__ void topk_k() {
    int r = blockIdx.x * 8 + (threadIdx.x >> 5);
    int lane = threadIdx.x & 31;
    if (r >= Nn) return;
    int g = r / NPGc;
    const float* row = g_sim + (size_t)g * NPGc * NPGc + (size_t)(r % NPGc) * NPGc;
    int goff = g * NPGc;
    float bv0 = -1e30f, bv1 = -1e30f, bv2 = -1e30f;
    int bi0 = 0x7fffffff, bi1 = 0x7fffffff, bi2 = 0x7fffffff;
    for (int j = lane; j < NPGc; j += 32) TK_INS(row[j], goff + j);
    for (int off = 16; off > 0; off >>= 1) {
        float ov0 = __shfl_down_sync(0xffffffff, bv0, off);
        float ov1 = __shfl_down_sync(0xffffffff, bv1, off);
        float ov2 = __shfl_down_sync(0xffffffff, bv2, off);
        int oi0 = __shfl_down_sync(0xffffffff, bi0, off);
        int oi1 = __shfl_down_sync(0xffffffff, bi1, off);
        int oi2 = __shfl_down_sync(0xffffffff, bi2, off);
        TK_INS(ov0, oi0); TK_INS(ov1, oi1); TK_INS(ov2, oi2);
    }
    if (lane == 0) {
        g_knn[r * 3 + 0] = bi0;
        g_knn[r * 3 + 1] = bi1;
        g_knn[r * 3 + 2] = bi2;
    }
}

// ---------------- CSR gather GCN aggregation (atomic-free) ----------------
__global__ void conv_gather_k(const float* __restrict__ bias) {
    int t = blockIdx.x * blockDim.x + threadIdx.x;
    if (t >= Nn * 64) return;
    int n = t >> 6, q = t & 63;
    float d0 = g_dinv[n];
    float co = d0 * d0;
    float4 a = ((const float4*)g_m)[(size_t)n * 64 + q];
    float4 bv = ((const float4*)bias)[q];
    float4 acc = make_float4(a.x * co + bv.x, a.y * co + bv.y,
                             a.z * co + bv.z, a.w * co + bv.w);
    int off = g_off[n], cnt = g_cnt[n];
    for (int j = 0; j < cnt; j++) {
        int s = g_esrc[off + j];
        float cf = g_ecoef[off + j];
        float4 v = ((const float4*)g_m)[(size_t)s * 64 + q];
        acc.x += v.x * cf; acc.y += v.y * cf; acc.z += v.z * cf; acc.w += v.w * cf;
    }
    ((float4*)g_c)[(size_t)n * 64 + q] = acc;
}

// knn branch: deg = K+1 = 4 uniformly -> coef = 0.25, gather
__global__ void knn_agg_k(const float* __restrict__ bias) {
    int t = blockIdx.x * blockDim.x + threadIdx.x;
    if (t >= Nn * 64) return;
    int n = t >> 6, q = t & 63;
    int i0 = g_knn[n * 3 + 0], i1 = g_knn[n * 3 + 1], i2 = g_knn[n * 3 + 2];
    float4 a = ((const float4*)g_m)[(size_t)n * 64 + q];
    float4 b = ((const float4*)g_m)[(size_t)i0 * 64 + q];
    float4 c = ((const float4*)g_m)[(size_t)i1 * 64 + q];
    float4 d = ((const float4*)g_m)[(size_t)i2 * 64 + q];
    float4 bv = ((const float4*)bias)[q];
    ((float4*)g_f)[(size_t)n * 64 + q] =
        make_float4(0.25f * (a.x + b.x + c.x + d.x) + bv.x,
                    0.25f * (a.y + b.y + c.y + d.y) + bv.y,
                    0.25f * (a.z + b.z + c.z + d.z) + bv.z,
                    0.25f * (a.w + b.w + c.w + d.w) + bv.w);
}

// ---------------- GraphNorm ----------------
__global__ void stats_k(const float* __restrict__ buf) {
    int b = blockIdx.x;
    int g = b / SPLIT, sp = b % SPLIT;
    int cc = threadIdx.x;
    int r0 = g * NPGc + sp * RPS;
    float s1 = 0.0f, s2 = 0.0f;
    for (int r = 0; r < RPS; r++) {
        float v = buf[(size_t)(r0 + r) * Hh + cc];
        s1 += v; s2 += v * v;
    }
    atomicAdd(&g_s1[g * Hh + cc], s1);
    atomicAdd(&g_s2[g * Hh + cc], s2);
}
__global__ void finalize_k(const float* __restrict__ w, const float* __restrict__ b,
                           const float* __restrict__ ms) {
    int i = blockIdx.x * blockDim.x + threadIdx.x;
    if (i >= Gg * Hh) return;
    int cc = i & 255;
    float mean = g_s1[i] * (1.0f / NPGc);
    float ex2 = g_s2[i] * (1.0f / NPGc);
    float m = ms[cc];
    float var = ex2 - mean * mean * m * (2.0f - m);
    float a = w[cc] * rsqrtf(var + 1e-5f);
    g_alpha[i] = a;
    g_beta[i] = b[cc] - a * m * mean;
}
__global__ void apply_leaky_k(float* __restrict__ buf) {
    int t = blockIdx.x * blockDim.x + threadIdx.x;
    if (t >= Nn * 64) return;
    int n = t >> 6, q = t & 63;
    int g = n / NPGc;
    float4 v = ((const float4*)buf)[(size_t)n * 64 + q];
    float4 a = ((const float4*)g_alpha)[(size_t)g * 64 + q];
    float4 b = ((const float4*)g_beta)[(size_t)g * 64 + q];
    float y0 = a.x * v.x + b.x, y1 = a.y * v.y + b.y;
    float y2 = a.z * v.z + b.z, y3 = a.w * v.w + b.w;
    y0 = y0 > 0.f ? y0 : 0.01f * y0;
    y1 = y1 > 0.f ? y1 : 0.01f * y1;
    y2 = y2 > 0.f ? y2 : 0.01f * y2;
    y3 = y3 > 0.f ? y3 : 0.01f * y3;
    ((float4*)buf)[(size_t)n * 64 + q] = make_float4(y0, y1, y2, y3);
}

// ---------------- pooling ----------------
__global__ void pool_k(const float* __restrict__ buf, float* __restrict__ out, float wgt) {
    int b = blockIdx.x;
    int g = b / SPLIT, sp = b % SPLIT;
    int cc = threadIdx.x;
    int r0 = g * NPGc + sp * RPS;
    float s = 0.0f;
    for (int r = 0; r < RPS; r++) s += buf[(size_t)(r0 + r) * Hh + cc];
    atomicAdd(&out[g * Hh + cc], s * wgt * (1.0f / NPGc));
}

// ---------------- launch ----------------
extern "C" void kernel_launch(void* const* d_in, const int* in_sizes, int n_in,
                              void* d_out, int out_size) {
    const float* x       = (const float*)d_in[0];
    const int*   ei      = (const int*)d_in[1];
    const float* emb_W   = (const float*)d_in[3];
    const float* emb_b   = (const float*)d_in[4];
    const float* conv_W  = (const float*)d_in[5];
    const float* conv_b  = (const float*)d_in[6];
    const float* fconv_W = (const float*)d_in[7];
    const float* fconv_b = (const float*)d_in[8];
    const float* norm_w  = (const float*)d_in[9];
    const float* norm_b  = (const float*)d_in[10];
    const float* norm_ms = (const float*)d_in[11];
    const float* fnorm_w = (const float*)d_in[12];
    const float* fnorm_b = (const float*)d_in[13];
    const float* fnorm_ms= (const float*)d_in[14];
    const float* gate_W  = (const float*)d_in[15];
    const float* gate_b  = (const float*)d_in[16];
    float* out = (float*)d_out;

    const int* src = ei;
    const int* dst = ei + Ee;

    float *h, *cbuf, *fbuf, *gbuf, *m;
    cudaGetSymbolAddress((void**)&h, g_h);
    cudaGetSymbolAddress((void**)&cbuf, g_c);
    cudaGetSymbolAddress((void**)&fbuf, g_f);
    cudaGetSymbolAddress((void**)&gbuf, g_g);
    cudaGetSymbolAddress((void**)&m, g_m);

    const int TPB = 256;
    const int MB = (Nn + 127) / 128;     // 391
    dim3 gemm_grid(2, MB);
    const int NBLK = (Nn + 255) / 256;   // 196

    zerof_k<<<(Gg * Hh + TPB - 1) / TPB, TPB>>>(out, Gg * Hh);

    // degrees + CSR build
    cnt_zero_k<<<NBLK, TPB>>>();
    cnt_count_k<<<(Ee + TPB - 1) / TPB, TPB>>>(dst);
    dinv_k<<<NBLK, TPB>>>();
    scan1_k<<<NBLK, 256>>>();
    scan2_k<<<1, 256>>>(NBLK);
    scan3_k<<<NBLK, TPB>>>();
    fill_k<<<(Ee + TPB - 1) / TPB, TPB>>>(src, dst);

    // h = x @ emb_W + emb_b  (fp32 — feeds discrete top-k)
    sgemm_emb_k<<<gemm_grid, TPB>>>(x, emb_W, h, Nn, INf, emb_b);

    // cosine knn (fp32 sim — must match reference top-k)
    rownorm_k<<<Nn, 64>>>();
    simbig_k<<<dim3(4, 4, Gg), TPB>>>();
    topk_k<<<(Nn + 7) / 8, TPB>>>();

    float pool_w[2] = {1.0f, 2.0f};   // gf = pool(x0) + 2*pool(x1)  (all_x[i-1] quirk)

    for (int li = 0; li < 2; li++) {
        // conv branch
        mmagemm_k<0><<<gemm_grid, TPB>>>(h, conv_W + li * Hh * Hh, m, Nn, nullptr,
                                         nullptr, nullptr, nullptr, nullptr, nullptr);
        conv_gather_k<<<(Nn * 64 + TPB - 1) / TPB, TPB>>>(conv_b + li * Hh);
        zstats_k<<<(Gg * Hh + TPB - 1) / TPB, TPB>>>();
        stats_k<<<Gg * SPLIT, TPB>>>(cbuf);
        finalize_k<<<(Gg * Hh + TPB - 1) / TPB, TPB>>>(norm_w + li * Hh, norm_b + li * Hh,
                                                       norm_ms + li * Hh);
        apply_leaky_k<<<(Nn * 64 + TPB - 1) / TPB, TPB>>>(cbuf);

        // feature branch
        mmagemm_k<0><<<gemm_grid, TPB>>>(cbuf, fconv_W + li * Hh * Hh, m, Nn, nullptr,
                                         nullptr, nullptr, nullptr, nullptr, nullptr);
        knn_agg_k<<<(Nn * 64 + TPB - 1) / TPB, TPB>>>(fconv_b + li * Hh);
        zstats_k<<<(Gg * Hh + TPB - 1) / TPB, TPB>>>();
        stats_k<<<Gg * SPLIT, TPB>>>(fbuf);
        finalize_k<<<(Gg * Hh + TPB - 1) / TPB, TPB>>>(fnorm_w + li * Hh, fnorm_b + li * Hh,
                                                       fnorm_ms + li * Hh);
        apply_leaky_k<<<(Nn * 64 + TPB - 1) / TPB, TPB>>>(fbuf);

        // gate + residual
        mmagemm_k<1><<<gemm_grid, TPB>>>(cbuf, gate_W, gbuf, Nn, gate_b,
                                         nullptr, nullptr, nullptr, nullptr, nullptr);
        mmagemm_k<2><<<gemm_grid, TPB>>>(fbuf, gate_W + Hh * Hh, nullptr, Nn, nullptr,
                                         gbuf, cbuf, fbuf, h, h);

        pool_k<<<Gg * SPLIT, TPB>>>(h, out, pool_w[li]);
    }
    (void)in_sizes; (void)n_in; (void)out_size;
}

// round 5
// speedup vs baseline: 2.2786x; 1.1730x over previous
#include <cuda_runtime.h>
#include <cuda_bf16.h>
#include <math.h>
#include <stdint.h>

#define Nn   50000
#define Gg   100
#define NPGc 500
#define INf  128
#define Hh   256
#define Ee   800000
#define SPLIT 10
#define RPS   50

// ---------------- scratch (static __device__, no allocs) ----------------
__device__ float g_h   [Nn * Hh];
__device__ float g_xn  [Nn * Hh];
__device__ __nv_bfloat16 g_mb [Nn * Hh];
__device__ float g_c   [Nn * Hh];
__device__ float g_f   [Nn * Hh];
__device__ float g_g   [Nn * Hh];
__device__ int   g_knn [Nn * 3];
__device__ int   g_cnt [Nn];
__device__ float g_dinv[Nn];
__device__ int   g_scan[Nn];
__device__ int   g_off [Nn];
__device__ int   g_fill[Nn];
__device__ int   g_bsum[256];
__device__ int   g_bbase[256];
__device__ int   g_esrc[Ee];
__device__ float g_ecoef[Ee];
__device__ float g_s1  [Gg * Hh];
__device__ float g_s2  [Gg * Hh];
__device__ float g_alpha[Gg * Hh];
__device__ float g_beta [Gg * Hh];
__device__ uint32_t g_wpack[6][128 * 256];   // bf16-pair-packed weights [kk][n]

// ---------------- small utility kernels ----------------
__global__ void zerof_k(float* p, int n) {
    int i = blockIdx.x * blockDim.x + threadIdx.x;
    if (i < n) p[i] = 0.0f;
}
__global__ void zstats_k() {
    int i = blockIdx.x * blockDim.x + threadIdx.x;
    if (i < Gg * Hh) { g_s1[i] = 0.0f; g_s2[i] = 0.0f; }
}
__global__ void cnt_zero_k() {
    int i = blockIdx.x * blockDim.x + threadIdx.x;
    if (i < Nn) g_cnt[i] = 0;
}
__global__ void cnt_count_k(const int* __restrict__ dst) {
    int e = blockIdx.x * blockDim.x + threadIdx.x;
    if (e < Ee) atomicAdd(&g_cnt[dst[e]], 1);
}
__global__ void dinv_k() {
    int i = blockIdx.x * blockDim.x + threadIdx.x;
    if (i < Nn) g_dinv[i] = rsqrtf((float)g_cnt[i] + 1.0f);
}

// pack W[256][256] fp32 -> Bp[kk][n] uint32 of bf16 pairs (k=2kk low, k=2kk+1 high)
__global__ void wpack_k(const float* __restrict__ W, int slot) {
    int i = blockIdx.x * blockDim.x + threadIdx.x;
    if (i >= 128 * 256) return;
    int kk = i >> 8, n = i & 255;
    __nv_bfloat162 p = __floats2bfloat162_rn(W[(2 * kk) * 256 + n], W[(2 * kk + 1) * 256 + n]);
    g_wpack[slot][i] = *(uint32_t*)&p;
}

// ---------------- CSR build (scan + fill) ----------------
__global__ void scan1_k() {
    __shared__ int sh[256];
    int i = blockIdx.x * 256 + threadIdx.x;
    int v = (i < Nn) ? g_cnt[i] : 0;
    sh[threadIdx.x] = v;
    __syncthreads();
    for (int off = 1; off < 256; off <<= 1) {
        int t = (threadIdx.x >= off) ? sh[threadIdx.x - off] : 0;
        __syncthreads();
        sh[threadIdx.x] += t;
        __syncthreads();
    }
    if (i < Nn) g_scan[i] = sh[threadIdx.x];
    if (threadIdx.x == 255) g_bsum[blockIdx.x] = sh[255];
}
__global__ void scan2_k(int nblk) {
    __shared__ int sh[256];
    int b = threadIdx.x;
    int v = (b < nblk) ? g_bsum[b] : 0;
    sh[b] = v;
    __syncthreads();
    for (int off = 1; off < 256; off <<= 1) {
        int t = (b >= off) ? sh[b - off] : 0;
        __syncthreads();
        sh[b] += t;
        __syncthreads();
    }
    if (b < nblk) g_bbase[b] = sh[b] - v;
}
__global__ void scan3_k() {
    int i = blockIdx.x * blockDim.x + threadIdx.x;
    if (i < Nn) {
        int off = g_scan[i] - g_cnt[i] + g_bbase[i >> 8];
        g_off[i] = off;
        g_fill[i] = off;
    }
}
__global__ void fill_k(const int* __restrict__ src, const int* __restrict__ dst) {
    int e = blockIdx.x * blockDim.x + threadIdx.x;
    if (e >= Ee) return;
    int s = src[e], d = dst[e];
    int p = atomicAdd(&g_fill[d], 1);
    g_esrc[p] = s;
    g_ecoef[p] = g_dinv[s] * g_dinv[d];
}

// ---------------- fp32 SGEMM for emb (feeds discrete top-k) ----------------
__global__ __launch_bounds__(256) void sgemm_emb_k(
    const float* __restrict__ A, const float* __restrict__ B, float* __restrict__ C,
    int M, int Kd, const float* __restrict__ bias)
{
    __shared__ float As[8][128];
    __shared__ float Bs[8][128];
    int tid = threadIdx.x;
    int m0 = blockIdx.y * 128, n0 = blockIdx.x * 128;
    int aRow = tid >> 1, aK = (tid & 1) * 4;
    int bRow = tid >> 5, bCol = (tid & 31) * 4;
    int tr = tid >> 4, tc = tid & 15;
    float acc[8][8];
#pragma unroll
    for (int i = 0; i < 8; i++)
#pragma unroll
        for (int j = 0; j < 8; j++) acc[i][j] = 0.0f;
    bool aval = (m0 + aRow) < M;
    const float* Abase = A + (size_t)(m0 + aRow) * Kd + aK;
    for (int k0 = 0; k0 < Kd; k0 += 8) {
        float4 av = aval ? *(const float4*)(Abase + k0) : make_float4(0.f, 0.f, 0.f, 0.f);
        As[aK + 0][aRow] = av.x; As[aK + 1][aRow] = av.y;
        As[aK + 2][aRow] = av.z; As[aK + 3][aRow] = av.w;
        float4 bv = *(const float4*)(B + (size_t)(k0 + bRow) * 256 + n0 + bCol);
        *(float4*)&Bs[bRow][bCol] = bv;
        __syncthreads();
#pragma unroll
        for (int kk = 0; kk < 8; kk++) {
            float a[8], b[8];
#pragma unroll
            for (int i = 0; i < 8; i++) a[i] = As[kk][tr * 8 + i];
#pragma unroll
            for (int j = 0; j < 8; j++) b[j] = Bs[kk][tc * 8 + j];
#pragma unroll
            for (int i = 0; i < 8; i++)
#pragma unroll
                for (int j = 0; j < 8; j++) acc[i][j] += a[i] * b[j];
        }
        __syncthreads();
    }
#pragma unroll
    for (int i = 0; i < 8; i++) {
        int row = m0 + tr * 8 + i;
        if (row >= M) break;
        size_t base = (size_t)row * 256 + n0 + tc * 8;
#pragma unroll
        for (int j = 0; j < 8; j++) C[base + j] = acc[i][j] + bias[n0 + tc * 8 + j];
    }
}

// ---------------- bf16 mma GEMM: [M,256] = A[M,256] @ Bp (+epilogue) ----------------
// EPI 0: write bf16 to mb
// EPI 1: C = acc + bias[col] (fp32)
// EPI 2: g = sigmoid(acc + gacc); hout = g*hc + (1-g)*fb + hprev
__device__ __forceinline__ uint32_t packbf2(float lo, float hi) {
    __nv_bfloat162 p = __floats2bfloat162_rn(lo, hi);
    return *(uint32_t*)&p;
}
__device__ __forceinline__ void mma16(float* c, const uint32_t* a, const uint32_t* b) {
    asm volatile(
        "mma.sync.aligned.m16n8k16.row.col.f32.bf16.bf16.f32 "
        "{%0,%1,%2,%3}, {%4,%5,%6,%7}, {%8,%9}, {%0,%1,%2,%3};"
        : "+f"(c[0]), "+f"(c[1]), "+f"(c[2]), "+f"(c[3])
        : "r"(a[0]), "r"(a[1]), "r"(a[2]), "r"(a[3]), "r"(b[0]), "r"(b[1]));
}

template <int EPI>
__global__ __launch_bounds__(256) void mmabf16_k(
    const float* __restrict__ A, const uint32_t* __restrict__ Bp,
    int M, const float* __restrict__ bias,
    const float* __restrict__ gacc, const float* __restrict__ hc,
    const float* __restrict__ fb, const float* __restrict__ hprev,
    float* __restrict__ fout, __nv_bfloat16* __restrict__ bout)
{
    __shared__ uint32_t As[128][20];    // [m][kpair], stride 20 -> conflict-free frags
    __shared__ uint32_t Bs[16][136];    // [kpair][n], stride 136 -> conflict-free frags

    int tid = threadIdx.x;
    int wid = tid >> 5, lane = tid & 31;
    int m0 = blockIdx.y * 128, n0 = blockIdx.x * 128;
    int wm = (wid & 3) * 32, wn = (wid >> 2) * 64;
    int group = lane >> 2, tig = lane & 3;

    float acc[2][8][4];
#pragma unroll
    for (int mt = 0; mt < 2; mt++)
#pragma unroll
        for (int nt = 0; nt < 8; nt++)
#pragma unroll
            for (int q = 0; q < 4; q++) acc[mt][nt][q] = 0.0f;

    int arow = tid >> 3, acK = (tid & 7) * 4;     // A: float4 at k0+acK, rows arow+32i
    int bkr = tid >> 4, bn8 = (tid & 15) * 8;     // B: kpair row bkr, cols bn8..bn8+7

    float4 pa[4];
    uint4 pb[2];
#pragma unroll
    for (int i = 0; i < 4; i++) {
        int r = m0 + arow + 32 * i;
        pa[i] = (r < M) ? *(const float4*)(A + (size_t)r * 256 + acK)
                        : make_float4(0.f, 0.f, 0.f, 0.f);
    }
#pragma unroll
    for (int j = 0; j < 2; j++)
        pb[j] = *(const uint4*)(Bp + (size_t)bkr * 256 + n0 + bn8 + 4 * j);

    for (int kt = 0; kt < 8; kt++) {
#pragma unroll
        for (int i = 0; i < 4; i++) {
            uint32_t u0 = packbf2(pa[i].x, pa[i].y);
            uint32_t u1 = packbf2(pa[i].z, pa[i].w);
            As[arow + 32 * i][(acK >> 1) + 0] = u0;
            As[arow + 32 * i][(acK >> 1) + 1] = u1;
        }
#pragma unroll
        for (int j = 0; j < 2; j++)
            *(uint4*)&Bs[bkr][bn8 + 4 * j] = pb[j];
        __syncthreads();

        if (kt < 7) {
            int k0 = (kt + 1) * 32;
#pragma unroll
            for (int i = 0; i < 4; i++) {
                int r = m0 + arow + 32 * i;
                pa[i] = (r < M) ? *(const float4*)(A + (size_t)r * 256 + k0 + acK)
                                : make_float4(0.f, 0.f, 0.f, 0.f);
            }
#pragma unroll
            for (int j = 0; j < 2; j++)
                pb[j] = *(const uint4*)(Bp + (size_t)((k0 >> 1) + bkr) * 256 + n0 + bn8 + 4 * j);
        }

#pragma unroll
        for (int s = 0; s < 2; s++) {
            uint32_t afr[2][4];
#pragma unroll
            for (int mt = 0; mt < 2; mt++) {
                int r = wm + mt * 16 + group;
                afr[mt][0] = As[r][s * 8 + tig];
                afr[mt][1] = As[r + 8][s * 8 + tig];
                afr[mt][2] = As[r][s * 8 + tig + 4];
                afr[mt][3] = As[r + 8][s * 8 + tig + 4];
            }
            uint32_t bfr[8][2];
#pragma unroll
            for (int nt = 0; nt < 8; nt++) {
                int cc = wn + nt * 8 + group;
                bfr[nt][0] = Bs[s * 8 + tig][cc];
                bfr[nt][1] = Bs[s * 8 + tig + 4][cc];
            }
#pragma unroll
            for (int mt = 0; mt < 2; mt++)
#pragma unroll
                for (int nt = 0; nt < 8; nt++) mma16(acc[mt][nt], afr[mt], bfr[nt]);
        }
        __syncthreads();
    }

#pragma unroll
    for (int mt = 0; mt < 2; mt++) {
#pragma unroll
        for (int half = 0; half < 2; half++) {
            int row = m0 + wm + mt * 16 + group + half * 8;
            if (row >= M) continue;
#pragma unroll
            for (int nt = 0; nt < 8; nt++) {
                int col = n0 + wn + nt * 8 + 2 * tig;
                float v0 = acc[mt][nt][half * 2 + 0];
                float v1 = acc[mt][nt][half * 2 + 1];
                size_t base = (size_t)row * 256 + col;
                if (EPI == 0) {
                    __nv_bfloat162 p = __floats2bfloat162_rn(v0, v1);
                    *(__nv_bfloat162*)(bout + base) = p;
                } else if (EPI == 1) {
                    fout[base] = v0 + bias[col];
                    fout[base + 1] = v1 + bias[col + 1];
                } else {
                    float s0 = v0 + gacc[base], s1 = v1 + gacc[base + 1];
                    float g0 = 1.0f / (1.0f + expf(-s0));
                    float g1 = 1.0f / (1.0f + expf(-s1));
                    fout[base]     = g0 * hc[base]     + (1.0f - g0) * fb[base]     + hprev[base];
                    fout[base + 1] = g1 * hc[base + 1] + (1.0f - g1) * fb[base + 1] + hprev[base + 1];
                }
            }
        }
    }
}

// ---------------- row normalize (for cosine knn) ----------------
__global__ void rownorm_k() {
    int row = blockIdx.x;
    int t = threadIdx.x;
    float4 v = *(const float4*)(g_h + (size_t)row * Hh + t * 4);
    float s = v.x * v.x + v.y * v.y + v.z * v.z + v.w * v.w;
    __shared__ float sh[64];
    sh[t] = s;
    __syncthreads();
    for (int off = 32; off > 0; off >>= 1) {
        if (t < off) sh[t] += sh[t + off];
        __syncthreads();
    }
    float inv = 1.0f / (sqrtf(sh[0]) + 1e-12f);
    *(float4*)(g_xn + (size_t)row * Hh + t * 4) =
        make_float4(v.x * inv, v.y * inv, v.z * inv, v.w * inv);
}

// ---------------- top-3 insert (jax top_k tie semantics: val desc, idx asc) ----------------
__device__ __forceinline__ void tk3(float v, int id, float* tv, int* ti) {
    if (v > tv[0] || (v == tv[0] && id < ti[0])) {
        tv[2] = tv[1]; ti[2] = ti[1];
        tv[1] = tv[0]; ti[1] = ti[0];
        tv[0] = v;     ti[0] = id;
    } else if (v > tv[1] || (v == tv[1] && id < ti[1])) {
        tv[2] = tv[1]; ti[2] = ti[1];
        tv[1] = v;     ti[1] = id;
    } else if (v > tv[2] || (v == tv[2] && id < ti[2])) {
        tv[2] = v;     ti[2] = id;
    }
}

// ---------------- fused sim + top-3 per graph (no sim materialization) ----------------
__global__ __launch_bounds__(256) void simtopk_k() {
    int g = blockIdx.y;
    int i0 = blockIdx.x * 128;
    const float* X = g_xn + (size_t)g * NPGc * Hh;
    int goff = g * NPGc;

    __shared__ float As[8][128];
    __shared__ float Bs[8][128];
    int tid = threadIdx.x;
    int lRow = tid >> 1, lK = (tid & 1) * 4;
    int tr = tid >> 4, tc = tid & 15;

    float tv[8][3];
    int ti[8][3];
#pragma unroll
    for (int i = 0; i < 8; i++)
#pragma unroll
        for (int c = 0; c < 3; c++) { tv[i][c] = -1e30f; ti[i][c] = 0x7fffffff; }

    bool avalid = (i0 + lRow) < NPGc;
    const float* Arow = X + (size_t)(i0 + lRow) * Hh + lK;

    for (int jt = 0; jt < 4; jt++) {
        int j0 = jt * 128;
        bool bvalid = (j0 + lRow) < NPGc;
        const float* Brow = X + (size_t)(j0 + lRow) * Hh + lK;

        float acc[8][8];
#pragma unroll
        for (int i = 0; i < 8; i++)
#pragma unroll
            for (int j = 0; j < 8; j++) acc[i][j] = 0.0f;

        for (int k0 = 0; k0 < Hh; k0 += 8) {
            float4 av = avalid ? *(const float4*)(Arow + k0) : make_float4(0.f, 0.f, 0.f, 0.f);
            As[lK + 0][lRow] = av.x; As[lK + 1][lRow] = av.y;
            As[lK + 2][lRow] = av.z; As[lK + 3][lRow] = av.w;
            float4 bv = bvalid ? *(const float4*)(Brow + k0) : make_float4(0.f, 0.f, 0.f, 0.f);
            Bs[lK + 0][lRow] = bv.x; Bs[lK + 1][lRow] = bv.y;
            Bs[lK + 2][lRow] = bv.z; Bs[lK + 3][lRow] = bv.w;
            __syncthreads();
#pragma unroll
            for (int kk = 0; kk < 8; kk++) {
                float a[8], b[8];
#pragma unroll
                for (int i = 0; i < 8; i++) a[i] = As[kk][tr * 8 + i];
#pragma unroll
                for (int j = 0; j < 8; j++) b[j] = Bs[kk][tc * 8 + j];
#pragma unroll
                for (int i = 0; i < 8; i++)
#pragma unroll
                    for (int j = 0; j < 8; j++) acc[i][j] += a[i] * b[j];
            }
            __syncthreads();
        }

        // merge this j-tile into per-row top-3
#pragma unroll
        for (int i = 0; i < 8; i++) {
#pragma unroll
            for (int j = 0; j < 8; j++) {
                int jg = j0 + tc * 8 + j;
                if (jg < NPGc) tk3(acc[i][j], goff + jg, tv[i], ti[i]);
            }
        }
    }

    // reduce across the 16 tc lanes (same tr = same 16-lane group within warp)
    for (int off = 8; off > 0; off >>= 1) {
#pragma unroll
        for (int i = 0; i < 8; i++) {
            float ov[3]; int oi[3];
#pragma unroll
            for (int c = 0; c < 3; c++) {
                ov[c] = __shfl_down_sync(0xffffffff, tv[i][c], off, 16);
                oi[c] = __shfl_down_sync(0xffffffff, ti[i][c], off, 16);
            }
#pragma unroll
            for (int c = 0; c < 3; c++) tk3(ov[c], oi[c], tv[i], ti[i]);
        }
    }

    if (tc == 0) {
#pragma unroll
        for (int i = 0; i < 8; i++) {
            int row = i0 + tr * 8 + i;
            if (row < NPGc) {
                int* o = g_knn + (size_t)(goff + row) * 3;
                o[0] = ti[i][0]; o[1] = ti[i][1]; o[2] = ti[i][2];
            }
        }
    }
}

// ---------------- CSR gather GCN aggregation (bf16 m, fp32 accumulate) ----------------
__device__ __forceinline__ float4 loadmb4(const __nv_bfloat16* p) {
    uint2 u = *(const uint2*)p;
    __nv_bfloat162 a = *(__nv_bfloat162*)&u.x;
    __nv_bfloat162 b = *(__nv_bfloat162*)&u.y;
    return make_float4(__bfloat162float(a.x), __bfloat162float(a.y),
                       __bfloat162float(b.x), __bfloat162float(b.y));
}

__global__ void conv_gather_k(const float* __restrict__ bias) {
    int t = blockIdx.x * blockDim.x + threadIdx.x;
    if (t >= Nn * 64) return;
    int n = t >> 6, q = t & 63;
    float d0 = g_dinv[n];
    float co = d0 * d0;
    float4 a = loadmb4(g_mb + (size_t)n * 256 + q * 4);
    float4 bv = ((const float4*)bias)[q];
    float4 acc = make_float4(a.x * co + bv.x, a.y * co + bv.y,
                             a.z * co + bv.z, a.w * co + bv.w);
    int off = g_off[n], cnt = g_cnt[n];
    for (int j = 0; j < cnt; j++) {
        int s = g_esrc[off + j];
        float cf = g_ecoef[off + j];
        float4 v = loadmb4(g_mb + (size_t)s * 256 + q * 4);
        acc.x += v.x * cf; acc.y += v.y * cf; acc.z += v.z * cf; acc.w += v.w * cf;
    }
    ((float4*)g_c)[(size_t)n * 64 + q] = acc;
}

__global__ void knn_agg_k(const float* __restrict__ bias) {
    int t = blockIdx.x * blockDim.x + threadIdx.x;
    if (t >= Nn * 64) return;
    int n = t >> 6, q = t & 63;
    int i0 = g_knn[n * 3 + 0], i1 = g_knn[n * 3 + 1], i2 = g_knn[n * 3 + 2];
    float4 a = loadmb4(g_mb + (size_t)n * 256 + q * 4);
    float4 b = loadmb4(g_mb + (size_t)i0 * 256 + q * 4);
    float4 c = loadmb4(g_mb + (size_t)i1 * 256 + q * 4);
    float4 d = loadmb4(g_mb + (size_t)i2 * 256 + q * 4);
    float4 bv = ((const float4*)bias)[q];
    ((float4*)g_f)[(size_t)n * 64 + q] =
        make_float4(0.25f * (a.x + b.x + c.x + d.x) + bv.x,
                    0.25f * (a.y + b.y + c.y + d.y) + bv.y,
                    0.25f * (a.z + b.z + c.z + d.z) + bv.z,
                    0.25f * (a.w + b.w + c.w + d.w) + bv.w);
}

// ---------------- GraphNorm ----------------
__global__ void stats_k(const float* __restrict__ buf) {
    int b = blockIdx.x;
    int g = b / SPLIT, sp = b % SPLIT;
    int cc = threadIdx.x;
    int r0 = g * NPGc + sp * RPS;
    float s1 = 0.0f, s2 = 0.0f;
    for (int r = 0; r < RPS; r++) {
        float v = buf[(size_t)(r0 + r) * Hh + cc];
        s1 += v; s2 += v * v;
    }
    atomicAdd(&g_s1[g * Hh + cc], s1);
    atomicAdd(&g_s2[g * Hh + cc], s2);
}
__global__ void finalize_k(const float* __restrict__ w, const float* __restrict__ b,
                           const float* __restrict__ ms) {
    int i = blockIdx.x * blockDim.x + threadIdx.x;
    if (i >= Gg * Hh) return;
    int cc = i & 255;
    float mean = g_s1[i] * (1.0f / NPGc);
    float ex2 = g_s2[i] * (1.0f / NPGc);
    float m = ms[cc];
    float var = ex2 - mean * mean * m * (2.0f - m);
    float a = w[cc] * rsqrtf(var + 1e-5f);
    g_alpha[i] = a;
    g_beta[i] = b[cc] - a * m * mean;
}
__global__ void apply_leaky_k(float* __restrict__ buf) {
    int t = blockIdx.x * blockDim.x + threadIdx.x;
    if (t >= Nn * 64) return;
    int n = t >> 6, q = t & 63;
    int g = n / NPGc;
    float4 v = ((const float4*)buf)[(size_t)n * 64 + q];
    float4 a = ((const float4*)g_alpha)[(size_t)g * 64 + q];
    float4 b = ((const float4*)g_beta)[(size_t)g * 64 + q];
    float y0 = a.x * v.x + b.x, y1 = a.y * v.y + b.y;
    float y2 = a.z * v.z + b.z, y3 = a.w * v.w + b.w;
    y0 = y0 > 0.f ? y0 : 0.01f * y0;
    y1 = y1 > 0.f ? y1 : 0.01f * y1;
    y2 = y2 > 0.f ? y2 : 0.01f * y2;
    y3 = y3 > 0.f ? y3 : 0.01f * y3;
    ((float4*)buf)[(size_t)n * 64 + q] = make_float4(y0, y1, y2, y3);
}

// ---------------- pooling ----------------
__global__ void pool_k(const float* __restrict__ buf, float* __restrict__ out, float wgt) {
    int b = blockIdx.x;
    int g = b / SPLIT, sp = b % SPLIT;
    int cc = threadIdx.x;
    int r0 = g * NPGc + sp * RPS;
    float s = 0.0f;
    for (int r = 0; r < RPS; r++) s += buf[(size_t)(r0 + r) * Hh + cc];
    atomicAdd(&out[g * Hh + cc], s * wgt * (1.0f / NPGc));
}

// ---------------- launch ----------------
extern "C" void kernel_launch(void* const* d_in, const int* in_sizes, int n_in,
                              void* d_out, int out_size) {
    const float* x       = (const float*)d_in[0];
    const int*   ei      = (const int*)d_in[1];
    const float* emb_W   = (const float*)d_in[3];
    const float* emb_b   = (const float*)d_in[4];
    const float* conv_W  = (const float*)d_in[5];
    const float* conv_b  = (const float*)d_in[6];
    const float* fconv_W = (const float*)d_in[7];
    const float* fconv_b = (const float*)d_in[8];
    const float* norm_w  = (const float*)d_in[9];
    const float* norm_b  = (const float*)d_in[10];
    const float* norm_ms = (const float*)d_in[11];
    const float* fnorm_w = (const float*)d_in[12];
    const float* fnorm_b = (const float*)d_in[13];
    const float* fnorm_ms= (const float*)d_in[14];
    const float* gate_W  = (const float*)d_in[15];
    const float* gate_b  = (const float*)d_in[16];
    float* out = (float*)d_out;

    const int* src = ei;
    const int* dst = ei + Ee;

    float *h, *cbuf, *fbuf, *gbuf;
    __nv_bfloat16* mb;
    uint32_t* wp;
    cudaGetSymbolAddress((void**)&h, g_h);
    cudaGetSymbolAddress((void**)&cbuf, g_c);
    cudaGetSymbolAddress((void**)&fbuf, g_f);
    cudaGetSymbolAddress((void**)&gbuf, g_g);
    cudaGetSymbolAddress((void**)&mb, g_mb);
    cudaGetSymbolAddress((void**)&wp, g_wpack);

    const int TPB = 256;
    const int MB = (Nn + 127) / 128;     // 391
    dim3 gemm_grid(2, MB);
    const int NBLK = (Nn + 255) / 256;   // 196
    const int WPB = (128 * 256 + TPB - 1) / TPB;

    zerof_k<<<(Gg * Hh + TPB - 1) / TPB, TPB>>>(out, Gg * Hh);

    // pack weights (bf16 pairs, transposed layout)
    wpack_k<<<WPB, TPB>>>(conv_W,             0);
    wpack_k<<<WPB, TPB>>>(conv_W + Hh * Hh,   1);
    wpack_k<<<WPB, TPB>>>(fconv_W,            2);
    wpack_k<<<WPB, TPB>>>(fconv_W + Hh * Hh,  3);
    wpack_k<<<WPB, TPB>>>(gate_W,             4);
    wpack_k<<<WPB, TPB>>>(gate_W + Hh * Hh,   5);

    // degrees + CSR build
    cnt_zero_k<<<NBLK, TPB>>>();
    cnt_count_k<<<(Ee + TPB - 1) / TPB, TPB>>>(dst);
    dinv_k<<<NBLK, TPB>>>();
    scan1_k<<<NBLK, 256>>>();
    scan2_k<<<1, 256>>>(NBLK);
    scan3_k<<<NBLK, TPB>>>();
    fill_k<<<(Ee + TPB - 1) / TPB, TPB>>>(src, dst);

    // h = x @ emb_W + emb_b (fp32)
    sgemm_emb_k<<<gemm_grid, TPB>>>(x, emb_W, h, Nn, INf, emb_b);

    // fused cosine knn: rownorm + sim + top3 (fp32, no sim materialization)
    rownorm_k<<<Nn, 64>>>();
    simtopk_k<<<dim3(4, Gg), TPB>>>();

    float pool_w[2] = {1.0f, 2.0f};   // gf = pool(x0) + 2*pool(x1)  (all_x[i-1] quirk)

    for (int li = 0; li < 2; li++) {
        // conv branch
        mmabf16_k<0><<<gemm_grid, TPB>>>(h, wp + (size_t)li * 128 * 256, Nn, nullptr,
                                         nullptr, nullptr, nullptr, nullptr, nullptr, mb);
        conv_gather_k<<<(Nn * 64 + TPB - 1) / TPB, TPB>>>(conv_b + li * Hh);
        zstats_k<<<(Gg * Hh + TPB - 1) / TPB, TPB>>>();
        stats_k<<<Gg * SPLIT, TPB>>>(cbuf);
        finalize_k<<<(Gg * Hh + TPB - 1) / TPB, TPB>>>(norm_w + li * Hh, norm_b + li * Hh,
                                                       norm_ms + li * Hh);
        apply_leaky_k<<<(Nn * 64 + TPB - 1) / TPB, TPB>>>(cbuf);

        // feature branch
        mmabf16_k<0><<<gemm_grid, TPB>>>(cbuf, wp + (size_t)(2 + li) * 128 * 256, Nn, nullptr,
                                         nullptr, nullptr, nullptr, nullptr, nullptr, mb);
        knn_agg_k<<<(Nn * 64 + TPB - 1) / TPB, TPB>>>(fconv_b + li * Hh);
        zstats_k<<<(Gg * Hh + TPB - 1) / TPB, TPB>>>();
        stats_k<<<Gg * SPLIT, TPB>>>(fbuf);
        finalize_k<<<(Gg * Hh + TPB - 1) / TPB, TPB>>>(fnorm_w + li * Hh, fnorm_b + li * Hh,
                                                       fnorm_ms + li * Hh);
        apply_leaky_k<<<(Nn * 64 + TPB - 1) / TPB, TPB>>>(fbuf);

        // gate + residual
        mmabf16_k<1><<<gemm_grid, TPB>>>(cbuf, wp + (size_t)4 * 128 * 256, Nn, gate_b,
                                         nullptr, nullptr, nullptr, nullptr, gbuf, nullptr);
        mmabf16_k<2><<<gemm_grid, TPB>>>(fbuf, wp + (size_t)5 * 128 * 256, Nn, nullptr,
                                         gbuf, cbuf, fbuf, h, h, nullptr);

        pool_k<<<Gg * SPLIT, TPB>>>(h, out, pool_w[li]);
    }
    (void)in_sizes; (void)n_in; (void)out_size;
}